// round 15
// baseline (speedup 1.0000x reference)
#include <cuda_runtime.h>
#include <cuda_bf16.h>
#include <cstdint>
#include <cstddef>

// Problem constants (fixed by the reference).
#define B_ROWS 32768
#define NDIM   64
#define HDIM   256
#define OFFDIM 2016   // 64*63/2

// ---------------------------------------------------------------------------
// Device scratch. h1 holds BOTH layer-1 outputs (d | o) as bf16 hi/lo split
// pairs: [M][16 chunks x 128B]. h2/h3 layer-2 outputs. diag/off fp32.
// ---------------------------------------------------------------------------
__device__ float g_h1[(size_t)B_ROWS * 512];
__device__ float g_h2[(size_t)B_ROWS * HDIM];
__device__ float g_h3[(size_t)B_ROWS * HDIM];
__device__ float g_diag[(size_t)B_ROWS * NDIM];
__device__ float g_off[(size_t)B_ROWS * OFFDIM];
__device__ __nv_bfloat16 g_xs[(size_t)B_ROWS * 2 * NDIM];  // x pre-split
__device__ float g_b1[512];                                 // concat(bd1,bo1)

// Split-chunked weights: per n-row, per 32-k group [hi 32 | lo 32] bf16.
#define WT_L1 0
#define WT_D2 32768
#define WT_O2 98304
#define WT_DO 163840
#define WT_OO 180224
#define WT_TOT 696320
__device__ __nv_bfloat16 g_wt[(size_t)2 * WT_TOT];

// ---------------------------------------------------------------------------
// Helpers
// ---------------------------------------------------------------------------
__device__ __forceinline__ uint32_t bf16x2_rn(float klo, float khi) {
    uint32_t r;  // low half <- klo (lower index), high half <- khi
    asm("cvt.rn.bf16x2.f32 %0, %1, %2;" : "=r"(r) : "f"(khi), "f"(klo));
    return r;
}
__device__ __forceinline__ void mma16(float* d, const uint32_t* a,
                                      const uint32_t* b) {
    asm volatile(
        "mma.sync.aligned.m16n8k16.row.col.f32.bf16.bf16.f32 "
        "{%0,%1,%2,%3}, {%4,%5,%6,%7}, {%8,%9}, {%0,%1,%2,%3};"
        : "+f"(d[0]), "+f"(d[1]), "+f"(d[2]), "+f"(d[3])
        : "r"(a[0]), "r"(a[1]), "r"(a[2]), "r"(a[3]), "r"(b[0]), "r"(b[1]));
}
__device__ __forceinline__ void ldsm4(uint32_t* r, uint32_t addr) {
    asm volatile(
        "ldmatrix.sync.aligned.m8n8.x4.shared.b16 {%0,%1,%2,%3}, [%4];"
        : "=r"(r[0]), "=r"(r[1]), "=r"(r[2]), "=r"(r[3]) : "r"(addr));
}
__device__ __forceinline__ uint32_t smem_u32(const void* p) {
    uint32_t a;
    asm("{ .reg .u64 t; cvta.to.shared.u64 t, %1; cvt.u32.u64 %0, t; }"
        : "=r"(a) : "l"(p));
    return a;
}
// Fast tanh: sign(x)*(1-e)/(1+e), e = exp(-2|x|). MUFU.EX2 path (~1e-6 rel;
// full tanhf is ~35 instr and dominated the tanh-GEMM epilogues per R14 ncu).
__device__ __forceinline__ float fast_tanh(float x) {
    float ax = fabsf(x);
    float e  = __expf(-2.0f * ax);
    float r  = __fdividef(1.0f - e, 1.0f + e);
    return copysignf(r, x);
}
#define CP16(d, s) \
    asm volatile("cp.async.cg.shared.global [%0], [%1], 16;" \
                 :: "r"(d), "l"(s))
#define CP16Z(d, s, sz) \
    asm volatile("cp.async.cg.shared.global [%0], [%1], 16, %2;" \
                 :: "r"(d), "l"(s), "r"(sz))
#define CP_COMMIT() asm volatile("cp.async.commit_group;" ::: "memory")
#define CP_WAIT2()  asm volatile("cp.async.wait_group 2;" ::: "memory")

enum { EPI_TANH = 0, EPI_BIAS = 1, EPI_DIAG = 2 };

// ---------------------------------------------------------------------------
// Prep 1: all weights -> split-chunked g_wt; concat bias -> g_b1.
// ---------------------------------------------------------------------------
__global__ void prep_w(const float* __restrict__ Wd1, const float* __restrict__ Wd2,
                       const float* __restrict__ Wdo, const float* __restrict__ Wo1,
                       const float* __restrict__ Wo2, const float* __restrict__ Woo,
                       const float* __restrict__ bd1, const float* __restrict__ bo1,
                       __nv_bfloat16* __restrict__ wt, float* __restrict__ b1) {
    int idx = blockIdx.x * 256 + threadIdx.x;
    if (idx < 512) b1[idx] = (idx < 256) ? bd1[idx] : bo1[idx - 256];
    if (idx >= WT_TOT) return;
    float w;
    int K, n, k, base;
    if (idx < 32768) {                       // L1: K=64, N=512
        base = WT_L1; K = 64;
        n = idx & 511; k = idx >> 9;
        w = (n < 256) ? Wd1[(size_t)k * 256 + n] : Wo1[(size_t)k * 256 + (n - 256)];
    } else if (idx < 98304) {                // D2: K=256, N=256
        base = WT_D2; K = 256;
        int local = idx - 32768;
        k = local / 256; n = local % 256;
        w = Wd2[(size_t)k * 256 + n];
    } else if (idx < 163840) {               // O2
        base = WT_O2; K = 256;
        int local = idx - 98304;
        k = local / 256; n = local % 256;
        w = Wo2[(size_t)k * 256 + n];
    } else if (idx < 180224) {               // DO: K=256, N=64
        base = WT_DO; K = 256;
        int local = idx - 163840;
        k = local / 64; n = local % 64;
        w = Wdo[(size_t)k * 64 + n];
    } else {                                 // OO: K=256, N=2016
        base = WT_OO; K = 256;
        int local = idx - 180224;
        k = local / 2016; n = local % 2016;
        w = Woo[(size_t)k * 2016 + n];
    }
    __nv_bfloat16* dst = wt + (size_t)2 * base + (size_t)n * 2 * K +
                         (k >> 5) * 64 + (k & 31);
    __nv_bfloat16 hb = __float2bfloat16_rn(w);
    dst[0]  = hb;
    dst[32] = __float2bfloat16_rn(w - __bfloat162float(hb));
}

// Prep 2: x -> split-chunked g_xs.
__global__ void prep_x(const float* __restrict__ x,
                       __nv_bfloat16* __restrict__ xs) {
    int idx = blockIdx.x * 256 + threadIdx.x;
    int m = idx >> 6, k = idx & 63;
    float w = x[(size_t)m * NDIM + k];
    __nv_bfloat16* dst = xs + (size_t)m * 128 + (k >> 5) * 64 + (k & 31);
    __nv_bfloat16 hb = __float2bfloat16_rn(w);
    dst[0]  = hb;
    dst[32] = __float2bfloat16_rn(w - __bfloat162float(hb));
}

// ---------------------------------------------------------------------------
// bf16x3 cp.async GEMM: C[M,N] = epi(A[M,K] @ W[K,N] + bias).
// BM=256, BN=128, BK=32; 256 threads = 8 warps (4Mx2N), warp tile 64x64.
// 4-stage cp.async pipeline. blockIdx.z selects operand set (0/1).
// R15: B-fragment double-buffer in mainloop (ldsm p+1 issued before MMAs of
// p); fast_tanh epilogue.
// ---------------------------------------------------------------------------
#define BM 256
#define BN 128
#define STAGEB 49152
#define SOFF_B 32768
#define LDP 132
#define GEMM_SMEM (4 * STAGEB)
#define NTHR 256

template <int EPI>
__global__ void __launch_bounds__(NTHR, 1)
gemm_mma(const __nv_bfloat16* __restrict__ A0, const __nv_bfloat16* __restrict__ A1,
         const __nv_bfloat16* __restrict__ B0, const __nv_bfloat16* __restrict__ B1,
         const float* __restrict__ bias0, const float* __restrict__ bias1,
         char* __restrict__ C0, char* __restrict__ C1,
         int lda, int K, int N, int ldc,
         const float* __restrict__ xin, const float* __restrict__ dmin) {
    extern __shared__ char smem[];
    const uint32_t sbase = smem_u32(smem);
    const int tid = threadIdx.x;
    const int wid = tid >> 5, lane = tid & 31;
    const int g = lane >> 2, tig = lane & 3;
    const int warpM = (wid >> 1) * 64;
    const int warpN = (wid & 1) * 64;
    const int m0 = blockIdx.y * BM;
    const int n0 = blockIdx.x * BN;

    const __nv_bfloat16* A4 = blockIdx.z ? A1 : A0;
    const __nv_bfloat16* B4 = blockIdx.z ? B1 : B0;
    const float* bias = blockIdx.z ? bias1 : bias0;
    char* C = blockIdx.z ? C1 : C0;

    const size_t K4a = (size_t)lda * 4;  // A row stride bytes
    const size_t K4b = (size_t)K * 4;    // B row stride bytes

    // Hoisted per-thread copy addressing.
    const int row0 = tid >> 3;           // 0..31
    const int sub  = tid & 7;
    const uint32_t dsw0 = (uint32_t)row0 * 128 +
                          (((uint32_t)sub ^ (row0 & 7)) << 4);
    const char* aBase = (const char*)A4 + (size_t)(m0 + row0) * K4a + sub * 16;
    const char* bBase = (const char*)B4 + (size_t)(n0 + row0) * K4b + sub * 16;

    // ldmatrix lane constants (validated R10/R12/R13).
    const uint32_t xorv = lane & 7;
    const int aRow = (lane & 7) + ((lane >> 3) & 1) * 8;
    const int aKq  = lane >> 4;
    const int bRow = (lane & 7) + ((lane >> 4) & 1) * 8;
    const int bKq  = (lane >> 3) & 1;

    float d[4][8][4];
#pragma unroll
    for (int mt = 0; mt < 4; mt++)
#pragma unroll
        for (int nt = 0; nt < 8; nt++)
#pragma unroll
            for (int j = 0; j < 4; j++) d[mt][nt][j] = 0.f;

    auto issue = [&](int t) {
        const int buf = (t & 3) * STAGEB;
        const char* ap = aBase + (size_t)t * 128;
#pragma unroll
        for (int i = 0; i < 8; i++)          // A rows row0 + 32i
            CP16(sbase + buf + dsw0 + i * 4096, ap + (size_t)i * 32 * K4a);
        const char* bp = bBase + (size_t)t * 128;
#pragma unroll
        for (int i = 0; i < 4; i++) {        // B rows row0 + 32i
            uint32_t sz = (n0 + row0 + 32 * i < N) ? 16u : 0u;  // 0 => zero-fill
            CP16Z(sbase + buf + SOFF_B + dsw0 + i * 4096,
                  bp + (size_t)i * 32 * K4b, sz);
        }
    };

    auto mma_chunk = [&](int b) {
        const uint32_t Ab = sbase + b * STAGEB;
        const uint32_t Bb = Ab + SOFF_B;
#pragma unroll
        for (int ks = 0; ks < 2; ks++) {
            const uint32_t ach = (((uint32_t)(ks * 2 + aKq)) ^ xorv) << 4;
            const uint32_t acl = (((uint32_t)(4 + ks * 2 + aKq)) ^ xorv) << 4;
            const uint32_t bch = (((uint32_t)(ks * 2 + bKq)) ^ xorv) << 4;
            const uint32_t bcl = (((uint32_t)(4 + ks * 2 + bKq)) ^ xorv) << 4;
            uint32_t ah[4][4], al[4][4];
#pragma unroll
            for (int mt = 0; mt < 4; mt++) {
                uint32_t ro = (uint32_t)(warpM + mt * 16 + aRow) * 128;
                ldsm4(ah[mt], Ab + ro + ach);
                ldsm4(al[mt], Ab + ro + acl);
            }
            // B-fragment double buffer: p+1 ldsm issues before p's MMAs.
            uint32_t bh[2][4], bl[2][4];
            {
                uint32_t ro = (uint32_t)(warpN + bRow) * 128;
                ldsm4(bh[0], Bb + ro + bch);
                ldsm4(bl[0], Bb + ro + bcl);
            }
#pragma unroll
            for (int p = 0; p < 4; p++) {
                const int cur = p & 1, nxt = cur ^ 1;
                if (p < 3) {
                    uint32_t ro = (uint32_t)(warpN + (p + 1) * 16 + bRow) * 128;
                    ldsm4(bh[nxt], Bb + ro + bch);
                    ldsm4(bl[nxt], Bb + ro + bcl);
                }
#pragma unroll
                for (int q = 0; q < 2; q++) {
                    const int nt = p * 2 + q;
#pragma unroll
                    for (int mt = 0; mt < 4; mt++) {
                        mma16(d[mt][nt], ah[mt], bh[cur] + q * 2);  // hi*hi
                        mma16(d[mt][nt], al[mt], bh[cur] + q * 2);  // lo*hi
                        mma16(d[mt][nt], ah[mt], bl[cur] + q * 2);  // hi*lo
                    }
                }
            }
        }
    };

    const int nT = K >> 5;
#pragma unroll
    for (int s = 0; s < 3; s++) {
        if (s < nT) issue(s);
        CP_COMMIT();
    }
    for (int t = 0; t < nT; t++) {
        CP_WAIT2();
        __syncthreads();
        if (t + 3 < nT) issue(t + 3);
        CP_COMMIT();
        mma_chunk(t & 3);
    }
    __syncthreads();

    // Epilogue: stage D tile [256][LDP] in smem (overlays stages).
    float* stg = reinterpret_cast<float*>(smem);
#pragma unroll
    for (int mt = 0; mt < 4; mt++)
#pragma unroll
        for (int nt = 0; nt < 8; nt++) {
            int r = warpM + mt * 16 + g;
            int c = warpN + nt * 8 + tig * 2;
            stg[r * LDP + c]           = d[mt][nt][0];
            stg[r * LDP + c + 1]       = d[mt][nt][1];
            stg[(r + 8) * LDP + c]     = d[mt][nt][2];
            stg[(r + 8) * LDP + c + 1] = d[mt][nt][3];
        }
    __syncthreads();

    // Warp-per-row stores: warp handles 32 rows; lane covers 16B -> coalesced.
    if (EPI == EPI_TANH) {
        // Split-chunk output: per row, 4 chunks x [hi 32 bf16 | lo 32 bf16].
        const int c = lane >> 3;
        const int h = (lane >> 2) & 1;
        const int s = lane & 3;
        const int eb = c * 32 + s * 8;
#pragma unroll 1
        for (int rr = 0; rr < 32; rr++) {
            const int row = wid + rr * 8;
            const float* sp = stg + row * LDP + eb;
            const float* bb = bias + n0 + eb;
            float v[8];
#pragma unroll
            for (int q = 0; q < 8; q++) v[q] = fast_tanh(sp[q] + bb[q]);
            uint4 pk;
            if (h == 0) {
                pk = make_uint4(bf16x2_rn(v[0], v[1]), bf16x2_rn(v[2], v[3]),
                                bf16x2_rn(v[4], v[5]), bf16x2_rn(v[6], v[7]));
            } else {
                float rf[8];
#pragma unroll
                for (int q = 0; q < 8; q++)
                    rf[q] = v[q] - __bfloat162float(__float2bfloat16_rn(v[q]));
                pk = make_uint4(bf16x2_rn(rf[0], rf[1]), bf16x2_rn(rf[2], rf[3]),
                                bf16x2_rn(rf[4], rf[5]), bf16x2_rn(rf[6], rf[7]));
            }
            char* rowp = C + (size_t)(m0 + row) * ((size_t)ldc * 4) +
                         ((size_t)(n0 >> 5)) * 128;
            *reinterpret_cast<uint4*>(rowp + c * 128 + h * 64 + s * 16) = pk;
        }
    } else {
        float* Cf = reinterpret_cast<float*>(C);
        const int col = lane * 4;
#pragma unroll 1
        for (int rr = 0; rr < 32; rr++) {
            const int row = wid + rr * 8;
            if (n0 + col < N) {
                const float* sp = stg + row * LDP + col;
                float v[4] = {sp[0], sp[1], sp[2], sp[3]};
#pragma unroll
                for (int q = 0; q < 4; q++) {
                    float val = v[q] + bias[n0 + col + q];
                    if (EPI == EPI_DIAG) {
                        float dd = fmaxf(val, 0.f) + dmin[n0 + col + q];
                        val = dd * xin[(size_t)(m0 + row) * NDIM + n0 + col + q];
                    }
                    v[q] = val;
                }
                *reinterpret_cast<float4*>(Cf + (size_t)(m0 + row) * ldc + n0 + col) =
                    make_float4(v[0], v[1], v[2], v[3]);
            }
        }
    }
}

// ---------------------------------------------------------------------------
// Final: out = L (L^T x) per batch row; L from (off, diag).
// ---------------------------------------------------------------------------
__global__ void __launch_bounds__(256)
final_kernel(const float* __restrict__ off, const float* __restrict__ diag,
             const float* __restrict__ x, float* __restrict__ out) {
    __shared__ float soff[4][OFFDIM];
    __shared__ float sx[4][NDIM];
    __shared__ float sd[4][NDIM];
    __shared__ float sv[4][NDIM];

    const int r    = threadIdx.x >> 6;
    const int lane = threadIdx.x & 63;
    const size_t row = (size_t)blockIdx.x * 4 + r;

    sx[r][lane] = x[row * NDIM + lane];
    sd[r][lane] = diag[row * NDIM + lane];
    const float* offr = off + row * OFFDIM;
    for (int i = lane; i < OFFDIM; i += 64) soff[r][i] = offr[i];
    __syncthreads();

    float v = sd[r][lane] * sx[r][lane];
    for (int i = lane + 1; i < NDIM; i++)
        v += soff[r][i * (i - 1) / 2 + lane] * sx[r][i];
    sv[r][lane] = v;
    __syncthreads();

    float o = sd[r][lane] * v;
    const int base = lane * (lane - 1) / 2;
    for (int j = 0; j < lane; j++) o += soff[r][base + j] * sv[r][j];
    out[row * NDIM + lane] = o;
}

// ---------------------------------------------------------------------------
// Launch. Order: prep_w(1), prep_x(2), L1(3), L2-batched(4), diag(5),
// Woo(6), final(7).
// ---------------------------------------------------------------------------
extern "C" void kernel_launch(void* const* d_in, const int* in_sizes, int n_in,
                              void* d_out, int out_size) {
    const float* x    = (const float*)d_in[0];
    const float* Wd1  = (const float*)d_in[1];
    const float* bd1  = (const float*)d_in[2];
    const float* Wd2  = (const float*)d_in[3];
    const float* bd2  = (const float*)d_in[4];
    const float* Wdo  = (const float*)d_in[5];
    const float* bdo  = (const float*)d_in[6];
    const float* Wo1  = (const float*)d_in[7];
    const float* bo1  = (const float*)d_in[8];
    const float* Wo2  = (const float*)d_in[9];
    const float* bo2  = (const float*)d_in[10];
    const float* Woo  = (const float*)d_in[11];
    const float* boo  = (const float*)d_in[12];
    const float* dmin = (const float*)d_in[13];
    float* out = (float*)d_out;

    float *h1, *h2, *h3, *dg, *off, *b1;
    __nv_bfloat16 *wt, *xs;
    cudaGetSymbolAddress((void**)&h1,  g_h1);
    cudaGetSymbolAddress((void**)&h2,  g_h2);
    cudaGetSymbolAddress((void**)&h3,  g_h3);
    cudaGetSymbolAddress((void**)&dg,  g_diag);
    cudaGetSymbolAddress((void**)&off, g_off);
    cudaGetSymbolAddress((void**)&wt,  g_wt);
    cudaGetSymbolAddress((void**)&xs,  g_xs);
    cudaGetSymbolAddress((void**)&b1,  g_b1);

    cudaFuncSetAttribute(gemm_mma<EPI_TANH>,
                         cudaFuncAttributeMaxDynamicSharedMemorySize, GEMM_SMEM);
    cudaFuncSetAttribute(gemm_mma<EPI_BIAS>,
                         cudaFuncAttributeMaxDynamicSharedMemorySize, GEMM_SMEM);
    cudaFuncSetAttribute(gemm_mma<EPI_DIAG>,
                         cudaFuncAttributeMaxDynamicSharedMemorySize, GEMM_SMEM);

    const int MB = B_ROWS / BM;  // 128 m-tiles

    // 1-2: prep (weights + concat bias; x split)
    prep_w<<<(WT_TOT + 255) / 256, 256>>>(Wd1, Wd2, Wdo, Wo1, Wo2, Woo,
                                          bd1, bo1, wt, b1);
    prep_x<<<(B_ROWS * NDIM) / 256, 256>>>(x, xs);

    // 3: layer-1 merged (K=64, N=512) -> h1 [M][512 split-chunk]
    gemm_mma<EPI_TANH><<<dim3(4, MB), NTHR, GEMM_SMEM>>>(
        xs, xs, wt + 2 * WT_L1, wt + 2 * WT_L1, b1, b1, (char*)h1, (char*)h1,
        64, 64, 512, 512, nullptr, nullptr);

    // 4: layer-2 batched (z=0: h1[:,0:256]@Wd2 -> h2;
    //                     z=1: h1[:,256:512]@Wo2 -> h3)
    gemm_mma<EPI_TANH><<<dim3(2, MB, 2), NTHR, GEMM_SMEM>>>(
        (const __nv_bfloat16*)h1, (const __nv_bfloat16*)h1 + 512,
        wt + 2 * WT_D2, wt + 2 * WT_O2, bd2, bo2, (char*)h2, (char*)h3,
        512, HDIM, HDIM, HDIM, nullptr, nullptr);

    // 5: diag output (K=256, N=64) -> dg fp32
    gemm_mma<EPI_DIAG><<<dim3(1, MB), NTHR, GEMM_SMEM>>>(
        (const __nv_bfloat16*)h2, (const __nv_bfloat16*)h2,
        wt + 2 * WT_DO, wt + 2 * WT_DO, bdo, bdo, (char*)dg, (char*)dg,
        HDIM, HDIM, NDIM, NDIM, x, dmin);

    // 6: dominant Woo GEMM (K=256, N=2016) -> off fp32
    gemm_mma<EPI_BIAS><<<dim3(16, MB), NTHR, GEMM_SMEM>>>(
        (const __nv_bfloat16*)h3, (const __nv_bfloat16*)h3,
        wt + 2 * WT_OO, wt + 2 * WT_OO, boo, boo, (char*)off, (char*)off,
        HDIM, HDIM, OFFDIM, OFFDIM, nullptr, nullptr);

    // 7: L (L^T x)
    final_kernel<<<B_ROWS / 4, 256>>>(off, dg, x, out);
}

// round 17
// speedup vs baseline: 1.0148x; 1.0148x over previous
#include <cuda_runtime.h>
#include <cuda_bf16.h>
#include <cstdint>
#include <cstddef>

// Problem constants (fixed by the reference).
#define B_ROWS 32768
#define NDIM   64
#define HDIM   256
#define OFFDIM 2016   // 64*63/2

// ---------------------------------------------------------------------------
// Device scratch. h1 holds BOTH layer-1 outputs (d | o) as bf16 hi/lo split
// pairs: [M][16 chunks x 128B]. h2/h3 layer-2 outputs. diag/off fp32.
// ---------------------------------------------------------------------------
__device__ float g_h1[(size_t)B_ROWS * 512];
__device__ float g_h2[(size_t)B_ROWS * HDIM];
__device__ float g_h3[(size_t)B_ROWS * HDIM];
__device__ float g_diag[(size_t)B_ROWS * NDIM];
__device__ float g_off[(size_t)B_ROWS * OFFDIM];
__device__ __nv_bfloat16 g_xs[(size_t)B_ROWS * 2 * NDIM];  // x pre-split
__device__ float g_b1[512];                                 // concat(bd1,bo1)

// Split-chunked weights: per n-row, per 32-k group [hi 32 | lo 32] bf16.
#define WT_L1 0
#define WT_D2 32768
#define WT_O2 98304
#define WT_DO 163840
#define WT_OO 180224
#define WT_TOT 696320
__device__ __nv_bfloat16 g_wt[(size_t)2 * WT_TOT];

// ---------------------------------------------------------------------------
// Helpers
// ---------------------------------------------------------------------------
__device__ __forceinline__ uint32_t bf16x2_rn(float klo, float khi) {
    uint32_t r;  // low half <- klo (lower index), high half <- khi
    asm("cvt.rn.bf16x2.f32 %0, %1, %2;" : "=r"(r) : "f"(khi), "f"(klo));
    return r;
}
__device__ __forceinline__ void mma16(float* d, const uint32_t* a,
                                      const uint32_t* b) {
    asm volatile(
        "mma.sync.aligned.m16n8k16.row.col.f32.bf16.bf16.f32 "
        "{%0,%1,%2,%3}, {%4,%5,%6,%7}, {%8,%9}, {%0,%1,%2,%3};"
        : "+f"(d[0]), "+f"(d[1]), "+f"(d[2]), "+f"(d[3])
        : "r"(a[0]), "r"(a[1]), "r"(a[2]), "r"(a[3]), "r"(b[0]), "r"(b[1]));
}
__device__ __forceinline__ void ldsm4(uint32_t* r, uint32_t addr) {
    asm volatile(
        "ldmatrix.sync.aligned.m8n8.x4.shared.b16 {%0,%1,%2,%3}, [%4];"
        : "=r"(r[0]), "=r"(r[1]), "=r"(r[2]), "=r"(r[3]) : "r"(addr));
}
__device__ __forceinline__ uint32_t smem_u32(const void* p) {
    uint32_t a;
    asm("{ .reg .u64 t; cvta.to.shared.u64 t, %1; cvt.u32.u64 %0, t; }"
        : "=r"(a) : "l"(p));
    return a;
}
// Fast tanh: sign(x)*(1-e)/(1+e), e = exp(-2|x|). MUFU path, ~1e-6 rel.
__device__ __forceinline__ float fast_tanh(float x) {
    float ax = fabsf(x);
    float e  = __expf(-2.0f * ax);
    float r  = __fdividef(1.0f - e, 1.0f + e);
    return copysignf(r, x);
}
#define CP16(d, s) \
    asm volatile("cp.async.cg.shared.global [%0], [%1], 16;" \
                 :: "r"(d), "l"(s))
#define CP16Z(d, s, sz) \
    asm volatile("cp.async.cg.shared.global [%0], [%1], 16, %2;" \
                 :: "r"(d), "l"(s), "r"(sz))
#define CP_COMMIT() asm volatile("cp.async.commit_group;" ::: "memory")
#define CP_WAIT0()  asm volatile("cp.async.wait_group 0;" ::: "memory")

enum { EPI_TANH = 0, EPI_BIAS = 1, EPI_DIAG = 2 };

// ---------------------------------------------------------------------------
// Prep 1: all weights -> split-chunked g_wt; concat bias -> g_b1.
// ---------------------------------------------------------------------------
__global__ void prep_w(const float* __restrict__ Wd1, const float* __restrict__ Wd2,
                       const float* __restrict__ Wdo, const float* __restrict__ Wo1,
                       const float* __restrict__ Wo2, const float* __restrict__ Woo,
                       const float* __restrict__ bd1, const float* __restrict__ bo1,
                       __nv_bfloat16* __restrict__ wt, float* __restrict__ b1) {
    int idx = blockIdx.x * 256 + threadIdx.x;
    if (idx < 512) b1[idx] = (idx < 256) ? bd1[idx] : bo1[idx - 256];
    if (idx >= WT_TOT) return;
    float w;
    int K, n, k, base;
    if (idx < 32768) {                       // L1: K=64, N=512
        base = WT_L1; K = 64;
        n = idx & 511; k = idx >> 9;
        w = (n < 256) ? Wd1[(size_t)k * 256 + n] : Wo1[(size_t)k * 256 + (n - 256)];
    } else if (idx < 98304) {                // D2: K=256, N=256
        base = WT_D2; K = 256;
        int local = idx - 32768;
        k = local / 256; n = local % 256;
        w = Wd2[(size_t)k * 256 + n];
    } else if (idx < 163840) {               // O2
        base = WT_O2; K = 256;
        int local = idx - 98304;
        k = local / 256; n = local % 256;
        w = Wo2[(size_t)k * 256 + n];
    } else if (idx < 180224) {               // DO: K=256, N=64
        base = WT_DO; K = 256;
        int local = idx - 163840;
        k = local / 64; n = local % 64;
        w = Wdo[(size_t)k * 64 + n];
    } else {                                 // OO: K=256, N=2016
        base = WT_OO; K = 256;
        int local = idx - 180224;
        k = local / 2016; n = local % 2016;
        w = Woo[(size_t)k * 2016 + n];
    }
    __nv_bfloat16* dst = wt + (size_t)2 * base + (size_t)n * 2 * K +
                         (k >> 5) * 64 + (k & 31);
    __nv_bfloat16 hb = __float2bfloat16_rn(w);
    dst[0]  = hb;
    dst[32] = __float2bfloat16_rn(w - __bfloat162float(hb));
}

// Prep 2: x -> split-chunked g_xs.
__global__ void prep_x(const float* __restrict__ x,
                       __nv_bfloat16* __restrict__ xs) {
    int idx = blockIdx.x * 256 + threadIdx.x;
    int m = idx >> 6, k = idx & 63;
    float w = x[(size_t)m * NDIM + k];
    __nv_bfloat16* dst = xs + (size_t)m * 128 + (k >> 5) * 64 + (k & 31);
    __nv_bfloat16 hb = __float2bfloat16_rn(w);
    dst[0]  = hb;
    dst[32] = __float2bfloat16_rn(w - __bfloat162float(hb));
}

// ---------------------------------------------------------------------------
// bf16x3 cp.async GEMM: C[M,N] = epi(A[M,K] @ W[K,N] + bias).
// BM=256, BN=128, BK=64; 256 threads = 8 warps (4Mx2N), warp tile 64x64.
// 2 stages x 64-k chunks (was 4 x 32-k) -> HALF the per-CTA barrier/wait
// count; per-chunk fixed exposure (R15-measured unexplained ~50% of CTA
// time) amortizes over 2x tensor work. Lookahead-1: issue(t+1) between
// wait and mma(t) so LDG latency hides under the MMA block.
// Stage row = 256B = two 128B split-chunks ([hi32|lo32] bf16 each).
//
// smem: 2 stages x (A 64KB | B 32KB) = 192KB; epilogue staging [256][132]
// fp32 (135KB) overlays the stages.
// ---------------------------------------------------------------------------
#define BM 256
#define BN 128
#define STAGEB 98304
#define SOFF_B 65536
#define LDP 132
#define GEMM_SMEM (2 * STAGEB)
#define NTHR 256

template <int EPI>
__global__ void __launch_bounds__(NTHR, 1)
gemm_mma(const __nv_bfloat16* __restrict__ A0, const __nv_bfloat16* __restrict__ A1,
         const __nv_bfloat16* __restrict__ B0, const __nv_bfloat16* __restrict__ B1,
         const float* __restrict__ bias0, const float* __restrict__ bias1,
         char* __restrict__ C0, char* __restrict__ C1,
         int lda, int K, int N, int ldc,
         const float* __restrict__ xin, const float* __restrict__ dmin) {
    extern __shared__ char smem[];
    const uint32_t sbase = smem_u32(smem);
    const int tid = threadIdx.x;
    const int wid = tid >> 5, lane = tid & 31;
    const int g = lane >> 2, tig = lane & 3;
    const int warpM = (wid >> 1) * 64;
    const int warpN = (wid & 1) * 64;
    const int m0 = blockIdx.y * BM;
    const int n0 = blockIdx.x * BN;

    const __nv_bfloat16* A4 = blockIdx.z ? A1 : A0;
    const __nv_bfloat16* B4 = blockIdx.z ? B1 : B0;
    const float* bias = blockIdx.z ? bias1 : bias0;
    char* C = blockIdx.z ? C1 : C0;

    const size_t K4a = (size_t)lda * 4;  // A row stride bytes
    const size_t K4b = (size_t)K * 4;    // B row stride bytes

    // Hoisted per-thread copy addressing. Stage row = 256B; swizzle is
    // per-128B-half (same XOR pattern as the gmem chunk layout).
    const int row0 = tid >> 3;           // 0..31
    const int sub  = tid & 7;
    const uint32_t dsw0 = (uint32_t)row0 * 256 +
                          (((uint32_t)sub ^ (row0 & 7)) << 4);
    const char* aBase = (const char*)A4 + (size_t)(m0 + row0) * K4a + sub * 16;
    const char* bBase = (const char*)B4 + (size_t)(n0 + row0) * K4b + sub * 16;

    // ldmatrix lane constants (validated R10/R12/R13).
    const uint32_t xorv = lane & 7;
    const int aRow = (lane & 7) + ((lane >> 3) & 1) * 8;
    const int aKq  = lane >> 4;
    const int bRow = (lane & 7) + ((lane >> 4) & 1) * 8;
    const int bKq  = (lane >> 3) & 1;

    float d[4][8][4];
#pragma unroll
    for (int mt = 0; mt < 4; mt++)
#pragma unroll
        for (int nt = 0; nt < 8; nt++)
#pragma unroll
            for (int j = 0; j < 4; j++) d[mt][nt][j] = 0.f;

    // Per stage (64 k): A 4096 + B 2048 16B pieces over 256 threads.
    auto issue = [&](int t) {
        const int buf = (t & 1) * STAGEB;
        const char* ap = aBase + (size_t)t * 256;
#pragma unroll
        for (int i = 0; i < 8; i++) {        // A rows row0 + 32i
#pragma unroll
            for (int hf = 0; hf < 2; hf++)
                CP16(sbase + buf + dsw0 + i * 8192 + hf * 128,
                     ap + (size_t)i * 32 * K4a + hf * 128);
        }
        const char* bp = bBase + (size_t)t * 256;
#pragma unroll
        for (int i = 0; i < 4; i++) {        // B rows row0 + 32i
            uint32_t sz = (n0 + row0 + 32 * i < N) ? 16u : 0u;  // 0 => zero-fill
#pragma unroll
            for (int hf = 0; hf < 2; hf++)
                CP16Z(sbase + buf + SOFF_B + dsw0 + i * 8192 + hf * 128,
                      bp + (size_t)i * 32 * K4b + hf * 128, sz);
        }
    };

    auto mma_chunk = [&](int b) {
        const uint32_t Ab = sbase + b * STAGEB;
        const uint32_t Bb = Ab + SOFF_B;
#pragma unroll
        for (int ks = 0; ks < 4; ks++) {     // 4 x k16 per 64-k chunk
            const uint32_t hf = (uint32_t)(ks >> 1) * 128;  // 128B half-row
            const int k2 = (ks & 1) * 2;
            const uint32_t ach = hf + ((((uint32_t)(k2 + aKq)) ^ xorv) << 4);
            const uint32_t acl = hf + ((((uint32_t)(4 + k2 + aKq)) ^ xorv) << 4);
            const uint32_t bch = hf + ((((uint32_t)(k2 + bKq)) ^ xorv) << 4);
            const uint32_t bcl = hf + ((((uint32_t)(4 + k2 + bKq)) ^ xorv) << 4);
            uint32_t ah[4][4], al[4][4];
#pragma unroll
            for (int mt = 0; mt < 4; mt++) {
                uint32_t ro = (uint32_t)(warpM + mt * 16 + aRow) * 256;
                ldsm4(ah[mt], Ab + ro + ach);
                ldsm4(al[mt], Ab + ro + acl);
            }
            // B-fragment double buffer: p+1 ldsm issues before p's MMAs.
            uint32_t bh[2][4], bl[2][4];
            {
                uint32_t ro = (uint32_t)(warpN + bRow) * 256;
                ldsm4(bh[0], Bb + ro + bch);
                ldsm4(bl[0], Bb + ro + bcl);
            }
#pragma unroll
            for (int p = 0; p < 4; p++) {
                const int cur = p & 1, nxt = cur ^ 1;
                if (p < 3) {
                    uint32_t ro = (uint32_t)(warpN + (p + 1) * 16 + bRow) * 256;
                    ldsm4(bh[nxt], Bb + ro + bch);
                    ldsm4(bl[nxt], Bb + ro + bcl);
                }
#pragma unroll
                for (int q = 0; q < 2; q++) {
                    const int nt = p * 2 + q;
#pragma unroll
                    for (int mt = 0; mt < 4; mt++) {
                        mma16(d[mt][nt], ah[mt], bh[cur] + q * 2);  // hi*hi
                        mma16(d[mt][nt], al[mt], bh[cur] + q * 2);  // lo*hi
                        mma16(d[mt][nt], ah[mt], bl[cur] + q * 2);  // hi*lo
                    }
                }
            }
        }
    };

    const int nT = K >> 6;                   // 64-k chunks
    issue(0);
    CP_COMMIT();
    for (int t = 0; t < nT; t++) {
        CP_WAIT0();                          // stage t landed (only g_t pends)
        __syncthreads();                     // visible; prior buf reads done
        if (t + 1 < nT) {                    // refill other buffer; overlaps
            issue(t + 1);                    // with mma(t) below
            CP_COMMIT();
        }
        mma_chunk(t & 1);
    }
    __syncthreads();

    // Epilogue: stage D tile [256][LDP] in smem (overlays stages).
    float* stg = reinterpret_cast<float*>(smem);
#pragma unroll
    for (int mt = 0; mt < 4; mt++)
#pragma unroll
        for (int nt = 0; nt < 8; nt++) {
            int r = warpM + mt * 16 + g;
            int c = warpN + nt * 8 + tig * 2;
            stg[r * LDP + c]           = d[mt][nt][0];
            stg[r * LDP + c + 1]       = d[mt][nt][1];
            stg[(r + 8) * LDP + c]     = d[mt][nt][2];
            stg[(r + 8) * LDP + c + 1] = d[mt][nt][3];
        }
    __syncthreads();

    // Warp-per-row stores: warp handles 32 rows; lane covers 16B -> coalesced.
    if (EPI == EPI_TANH) {
        // Split-chunk output: per row, 4 chunks x [hi 32 bf16 | lo 32 bf16].
        const int c = lane >> 3;
        const int h = (lane >> 2) & 1;
        const int s = lane & 3;
        const int eb = c * 32 + s * 8;
#pragma unroll 1
        for (int rr = 0; rr < 32; rr++) {
            const int row = wid + rr * 8;
            const float* sp = stg + row * LDP + eb;
            const float* bb = bias + n0 + eb;
            float v[8];
#pragma unroll
            for (int q = 0; q < 8; q++) v[q] = fast_tanh(sp[q] + bb[q]);
            uint4 pk;
            if (h == 0) {
                pk = make_uint4(bf16x2_rn(v[0], v[1]), bf16x2_rn(v[2], v[3]),
                                bf16x2_rn(v[4], v[5]), bf16x2_rn(v[6], v[7]));
            } else {
                float rf[8];
#pragma unroll
                for (int q = 0; q < 8; q++)
                    rf[q] = v[q] - __bfloat162float(__float2bfloat16_rn(v[q]));
                pk = make_uint4(bf16x2_rn(rf[0], rf[1]), bf16x2_rn(rf[2], rf[3]),
                                bf16x2_rn(rf[4], rf[5]), bf16x2_rn(rf[6], rf[7]));
            }
            char* rowp = C + (size_t)(m0 + row) * ((size_t)ldc * 4) +
                         ((size_t)(n0 >> 5)) * 128;
            *reinterpret_cast<uint4*>(rowp + c * 128 + h * 64 + s * 16) = pk;
        }
    } else {
        float* Cf = reinterpret_cast<float*>(C);
        const int col = lane * 4;
#pragma unroll 1
        for (int rr = 0; rr < 32; rr++) {
            const int row = wid + rr * 8;
            if (n0 + col < N) {
                const float* sp = stg + row * LDP + col;
                float v[4] = {sp[0], sp[1], sp[2], sp[3]};
#pragma unroll
                for (int q = 0; q < 4; q++) {
                    float val = v[q] + bias[n0 + col + q];
                    if (EPI == EPI_DIAG) {
                        float dd = fmaxf(val, 0.f) + dmin[n0 + col + q];
                        val = dd * xin[(size_t)(m0 + row) * NDIM + n0 + col + q];
                    }
                    v[q] = val;
                }
                *reinterpret_cast<float4*>(Cf + (size_t)(m0 + row) * ldc + n0 + col) =
                    make_float4(v[0], v[1], v[2], v[3]);
            }
        }
    }
}

// ---------------------------------------------------------------------------
// Final: out = L (L^T x) per batch row; L from (off, diag).
// ---------------------------------------------------------------------------
__global__ void __launch_bounds__(256)
final_kernel(const float* __restrict__ off, const float* __restrict__ diag,
             const float* __restrict__ x, float* __restrict__ out) {
    __shared__ float soff[4][OFFDIM];
    __shared__ float sx[4][NDIM];
    __shared__ float sd[4][NDIM];
    __shared__ float sv[4][NDIM];

    const int r    = threadIdx.x >> 6;
    const int lane = threadIdx.x & 63;
    const size_t row = (size_t)blockIdx.x * 4 + r;

    sx[r][lane] = x[row * NDIM + lane];
    sd[r][lane] = diag[row * NDIM + lane];
    const float* offr = off + row * OFFDIM;
    for (int i = lane; i < OFFDIM; i += 64) soff[r][i] = offr[i];
    __syncthreads();

    float v = sd[r][lane] * sx[r][lane];
    for (int i = lane + 1; i < NDIM; i++)
        v += soff[r][i * (i - 1) / 2 + lane] * sx[r][i];
    sv[r][lane] = v;
    __syncthreads();

    float o = sd[r][lane] * v;
    const int base = lane * (lane - 1) / 2;
    for (int j = 0; j < lane; j++) o += soff[r][base + j] * sv[r][j];
    out[row * NDIM + lane] = o;
}

// ---------------------------------------------------------------------------
// Launch. Order: prep_w(1), prep_x(2), L1(3), L2-batched(4), diag(5),
// Woo(6), final(7).
// ---------------------------------------------------------------------------
extern "C" void kernel_launch(void* const* d_in, const int* in_sizes, int n_in,
                              void* d_out, int out_size) {
    const float* x    = (const float*)d_in[0];
    const float* Wd1  = (const float*)d_in[1];
    const float* bd1  = (const float*)d_in[2];
    const float* Wd2  = (const float*)d_in[3];
    const float* bd2  = (const float*)d_in[4];
    const float* Wdo  = (const float*)d_in[5];
    const float* bdo  = (const float*)d_in[6];
    const float* Wo1  = (const float*)d_in[7];
    const float* bo1  = (const float*)d_in[8];
    const float* Wo2  = (const float*)d_in[9];
    const float* bo2  = (const float*)d_in[10];
    const float* Woo  = (const float*)d_in[11];
    const float* boo  = (const float*)d_in[12];
    const float* dmin = (const float*)d_in[13];
    float* out = (float*)d_out;

    float *h1, *h2, *h3, *dg, *off, *b1;
    __nv_bfloat16 *wt, *xs;
    cudaGetSymbolAddress((void**)&h1,  g_h1);
    cudaGetSymbolAddress((void**)&h2,  g_h2);
    cudaGetSymbolAddress((void**)&h3,  g_h3);
    cudaGetSymbolAddress((void**)&dg,  g_diag);
    cudaGetSymbolAddress((void**)&off, g_off);
    cudaGetSymbolAddress((void**)&wt,  g_wt);
    cudaGetSymbolAddress((void**)&xs,  g_xs);
    cudaGetSymbolAddress((void**)&b1,  g_b1);

    cudaFuncSetAttribute(gemm_mma<EPI_TANH>,
                         cudaFuncAttributeMaxDynamicSharedMemorySize, GEMM_SMEM);
    cudaFuncSetAttribute(gemm_mma<EPI_BIAS>,
                         cudaFuncAttributeMaxDynamicSharedMemorySize, GEMM_SMEM);
    cudaFuncSetAttribute(gemm_mma<EPI_DIAG>,
                         cudaFuncAttributeMaxDynamicSharedMemorySize, GEMM_SMEM);

    const int MB = B_ROWS / BM;  // 128 m-tiles

    // 1-2: prep (weights + concat bias; x split)
    prep_w<<<(WT_TOT + 255) / 256, 256>>>(Wd1, Wd2, Wdo, Wo1, Wo2, Woo,
                                          bd1, bo1, wt, b1);
    prep_x<<<(B_ROWS * NDIM) / 256, 256>>>(x, xs);

    // 3: layer-1 merged (K=64, N=512) -> h1 [M][512 split-chunk]
    gemm_mma<EPI_TANH><<<dim3(4, MB), NTHR, GEMM_SMEM>>>(
        xs, xs, wt + 2 * WT_L1, wt + 2 * WT_L1, b1, b1, (char*)h1, (char*)h1,
        64, 64, 512, 512, nullptr, nullptr);

    // 4: layer-2 batched (z=0: h1[:,0:256]@Wd2 -> h2;
    //                     z=1: h1[:,256:512]@Wo2 -> h3)
    gemm_mma<EPI_TANH><<<dim3(2, MB, 2), NTHR, GEMM_SMEM>>>(
        (const __nv_bfloat16*)h1, (const __nv_bfloat16*)h1 + 512,
        wt + 2 * WT_D2, wt + 2 * WT_O2, bd2, bo2, (char*)h2, (char*)h3,
        512, HDIM, HDIM, HDIM, nullptr, nullptr);

    // 5: diag output (K=256, N=64) -> dg fp32
    gemm_mma<EPI_DIAG><<<dim3(1, MB), NTHR, GEMM_SMEM>>>(
        (const __nv_bfloat16*)h2, (const __nv_bfloat16*)h2,
        wt + 2 * WT_DO, wt + 2 * WT_DO, bdo, bdo, (char*)dg, (char*)dg,
        HDIM, HDIM, NDIM, NDIM, x, dmin);

    // 6: dominant Woo GEMM (K=256, N=2016) -> off fp32
    gemm_mma<EPI_BIAS><<<dim3(16, MB), NTHR, GEMM_SMEM>>>(
        (const __nv_bfloat16*)h3, (const __nv_bfloat16*)h3,
        wt + 2 * WT_OO, wt + 2 * WT_OO, boo, boo, (char*)off, (char*)off,
        HDIM, HDIM, OFFDIM, OFFDIM, nullptr, nullptr);

    // 7: L (L^T x)
    final_kernel<<<B_ROWS / 4, 256>>>(off, dg, x, out);
}